// round 1
// baseline (speedup 1.0000x reference)
#include <cuda_runtime.h>
#include <cuda_bf16.h>
#include <math.h>

#define BB 16
#define LL 512
#define DD 768
#define HH 4
#define AA 100
#define DK 25
#define PP 3
#define EPS 1e-6f

// ---------------- scratch (device globals; no allocation allowed) ----------------
__device__ float g_seqn[BB * LL * DD];        // 25 MB
__device__ float g_x   [BB * LL * AA];
__device__ float g_q   [BB * LL * AA];
__device__ float g_k   [BB * LL * AA];
__device__ float g_scores[(size_t)BB * HH * LL * LL];  // 67 MB
__device__ float g_adjm[(size_t)BB * LL * LL];         // mean_h adj
__device__ float g_adjc[(size_t)BB * LL * LL];         // sum_h c[h] adj
__device__ float g_Ax  [BB * LL * AA];
__device__ float g_x1  [BB * LL * AA];
__device__ float g_x2  [BB * LL * AA];
__device__ float g_feats[BB * LL * 3 * AA];
__device__ float g_node[BB * LL * AA];
__device__ float g_pooled[BB * AA];
__device__ float g_cbuf[HH];
__device__ float g_b1m[AA];
__device__ float g_b2m[AA];
__device__ float g_bm[1];
__device__ float g_um[BB * LL];
__device__ float g_vm[BB * LL];
__device__ float g_S[BB * AA];
__device__ float g_U[BB * AA];

// ---------------- small precompute: c[h], b1m, b2m, bm ----------------
__global__ void pre_kernel(const float* __restrict__ Wx_w, const float* __restrict__ Wx_b)
{
    int t = threadIdx.x;
    const int LDW = HH + 2 * AA;  // 204
    if (t < HH) {
        float s = 0.f;
        for (int g = 0; g < HH; g++) s += Wx_w[g * LDW + t];
        g_cbuf[t] = s * 0.25f;
    }
    if (t < AA) {
        float s1 = 0.f, s2 = 0.f;
        for (int g = 0; g < HH; g++) {
            s1 += Wx_w[g * LDW + HH + t];
            s2 += Wx_w[g * LDW + HH + AA + t];
        }
        g_b1m[t] = s1 * 0.25f;
        g_b2m[t] = s2 * 0.25f;
    }
    if (t == 0) {
        float s = 0.f;
        for (int g = 0; g < HH; g++) s += Wx_b[g];
        g_bm[0] = s * 0.25f;
    }
}

// ---------------- LayerNorm (ddof=1, eps added to std) ----------------
__global__ void ln_kernel(const float* __restrict__ x, const float* __restrict__ a,
                          const float* __restrict__ bvec)
{
    int row = blockIdx.x;                 // B*L rows
    const float* xr = x + (size_t)row * DD;
    float* yr = g_seqn + (size_t)row * DD;
    int t = threadIdx.x;                  // 256 threads, 3 elems each
    __shared__ float red[16];
    float v0 = xr[t], v1 = xr[t + 256], v2 = xr[t + 512];
    float s = v0 + v1 + v2;
    float ss = v0 * v0 + v1 * v1 + v2 * v2;
    // warp reduce both
    for (int o = 16; o; o >>= 1) {
        s  += __shfl_xor_sync(0xffffffffu, s, o);
        ss += __shfl_xor_sync(0xffffffffu, ss, o);
    }
    int w = t >> 5;
    if ((t & 31) == 0) { red[w] = s; red[8 + w] = ss; }
    __syncthreads();
    float S = 0.f, SS = 0.f;
    #pragma unroll
    for (int i = 0; i < 8; i++) { S += red[i]; SS += red[8 + i]; }
    float mean = S / (float)DD;
    float var = (SS - (float)DD * mean * mean) / (float)(DD - 1);
    var = fmaxf(var, 0.f);
    float inv = 1.f / (sqrtf(var) + EPS);
    yr[t]       = a[t]       * (v0 - mean) * inv + bvec[t];
    yr[t + 256] = a[t + 256] * (v1 - mean) * inv + bvec[t + 256];
    yr[t + 512] = a[t + 512] * (v2 - mean) * inv + bvec[t + 512];
}

// ---------------- generic C = act(A(M,K) @ B(N,K)^T + bias) ----------------
__global__ void gemm_nt_kernel(const float* __restrict__ A, const float* __restrict__ Bm,
                               const float* __restrict__ bias, float* __restrict__ C,
                               int M, int N, int K, int act)
{
    __shared__ __align__(16) float As[16][68];
    __shared__ __align__(16) float Bs[16][64];
    int t = threadIdx.x;
    int tx = t & 15, ty = t >> 4;
    int m0 = blockIdx.y * 64, n0 = blockIdx.x * 64;
    int lr = t >> 2;            // 0..63
    int lc = (t & 3) * 4;       // 0,4,8,12
    float acc[4][4];
    #pragma unroll
    for (int i = 0; i < 4; i++)
        #pragma unroll
        for (int j = 0; j < 4; j++) acc[i][j] = 0.f;

    for (int k0 = 0; k0 < K; k0 += 16) {
        int arow = m0 + lr;
        int brow = n0 + lr;
        #pragma unroll
        for (int i = 0; i < 4; i++) {
            int kk = k0 + lc + i;
            As[lc + i][lr] = (arow < M && kk < K) ? A[(size_t)arow * K + kk] : 0.f;
            Bs[lc + i][lr] = (brow < N && kk < K) ? Bm[(size_t)brow * K + kk] : 0.f;
        }
        __syncthreads();
        #pragma unroll
        for (int k = 0; k < 16; k++) {
            float a[4], b[4];
            #pragma unroll
            for (int i = 0; i < 4; i++) a[i] = As[k][ty * 4 + i];
            float4 bv = *(const float4*)&Bs[k][tx * 4];
            b[0] = bv.x; b[1] = bv.y; b[2] = bv.z; b[3] = bv.w;
            #pragma unroll
            for (int i = 0; i < 4; i++)
                #pragma unroll
                for (int j = 0; j < 4; j++) acc[i][j] += a[i] * b[j];
        }
        __syncthreads();
    }
    #pragma unroll
    for (int i = 0; i < 4; i++) {
        int row = m0 + ty * 4 + i;
        if (row >= M) continue;
        #pragma unroll
        for (int j = 0; j < 4; j++) {
            int col = n0 + tx * 4 + j;
            if (col >= N) continue;
            float v = acc[i][j] + bias[col];
            if (act) v = fmaxf(v, 0.f);
            C[(size_t)row * N + col] = v;
        }
    }
}

// ---------------- batched C[b] = A[b](M,K) @ B[b](K,N) (+ rank-1 epilogue) ----------------
__global__ void gemm_nn_b_kernel(const float* __restrict__ Ag, const float* __restrict__ Bg,
                                 float* __restrict__ Cg,
                                 int M, int N, int K, int sA, int sB, int sC,
                                 const float* __restrict__ U, const float* __restrict__ S,
                                 const float* __restrict__ vm, const float* __restrict__ bmp)
{
    int b = blockIdx.z;
    const float* A = Ag + (size_t)b * sA;
    const float* Bm = Bg + (size_t)b * sB;
    float* C = Cg + (size_t)b * sC;
    __shared__ __align__(16) float As[16][68];
    __shared__ __align__(16) float Bs[16][64];
    int t = threadIdx.x;
    int tx = t & 15, ty = t >> 4;
    int m0 = blockIdx.y * 64, n0 = blockIdx.x * 64;
    int lr = t >> 2;
    int lc = (t & 3) * 4;
    int kr = t >> 4;            // 0..15
    int nc = (t & 15) * 4;      // 0..60
    float acc[4][4];
    #pragma unroll
    for (int i = 0; i < 4; i++)
        #pragma unroll
        for (int j = 0; j < 4; j++) acc[i][j] = 0.f;

    for (int k0 = 0; k0 < K; k0 += 16) {
        #pragma unroll
        for (int i = 0; i < 4; i++) {
            int kk = k0 + lc + i;
            As[lc + i][lr] = A[(size_t)(m0 + lr) * K + kk];    // M,K multiples of tile
        }
        #pragma unroll
        for (int i = 0; i < 4; i++) {
            int n = n0 + nc + i;
            Bs[kr][nc + i] = (n < N) ? Bm[(size_t)(k0 + kr) * N + n] : 0.f;
        }
        __syncthreads();
        #pragma unroll
        for (int k = 0; k < 16; k++) {
            float a[4], bfr[4];
            #pragma unroll
            for (int i = 0; i < 4; i++) a[i] = As[k][ty * 4 + i];
            float4 bv = *(const float4*)&Bs[k][tx * 4];
            bfr[0] = bv.x; bfr[1] = bv.y; bfr[2] = bv.z; bfr[3] = bv.w;
            #pragma unroll
            for (int i = 0; i < 4; i++)
                #pragma unroll
                for (int j = 0; j < 4; j++) acc[i][j] += a[i] * bfr[j];
        }
        __syncthreads();
    }
    float bmv = (U != nullptr) ? bmp[0] : 0.f;
    #pragma unroll
    for (int i = 0; i < 4; i++) {
        int row = m0 + ty * 4 + i;
        #pragma unroll
        for (int j = 0; j < 4; j++) {
            int col = n0 + tx * 4 + j;
            if (col >= N) continue;
            float v = acc[i][j];
            if (U != nullptr)
                v += U[b * AA + col] + (vm[b * LL + row] + bmv) * S[b * AA + col];
            C[(size_t)row * N + col] = v;
        }
    }
}

// ---------------- scores = QK^T/sqrt(DK)  (mask)  + syntax ----------------
__global__ void scores_kernel(const float* __restrict__ syn, const int* __restrict__ src_mask)
{
    int bh = blockIdx.z;
    int b = bh >> 2, h = bh & 3;
    int i0 = blockIdx.y * 32, j0 = blockIdx.x * 32;
    __shared__ float qs[32][26], ks[32][26];
    int t = threadIdx.x;
    for (int idx = t; idx < 32 * DK; idx += 256) {
        int r = idx / DK, c = idx % DK;
        qs[r][c] = g_q[(size_t)(b * LL + i0 + r) * AA + h * DK + c];
        ks[r][c] = g_k[(size_t)(b * LL + j0 + r) * AA + h * DK + c];
    }
    __syncthreads();
    int i = t >> 3, jb = (t & 7) * 4;
    float qr[DK];
    #pragma unroll
    for (int c = 0; c < DK; c++) qr[c] = qs[i][c];
    #pragma unroll
    for (int jj = 0; jj < 4; jj++) {
        int j = jb + jj;
        float acc = 0.f;
        #pragma unroll
        for (int c = 0; c < DK; c++) acc += qr[c] * ks[j][c];
        float v = acc * 0.2f;                       // 1/sqrt(25)
        if (src_mask[b * LL + j0 + j] == 0) v = -1e9f;
        size_t off = ((size_t)(b * HH + h) * LL + (i0 + i)) * LL + (j0 + j);
        v += syn[off];
        g_scores[off] = v;
    }
}

// ---------------- softmax over j + fold heads into adjm (mean) & adjc (c-weighted) ----------------
__global__ void softmax_combine_kernel()
{
    int bi = blockIdx.x;            // b*L + i
    int t = threadIdx.x;            // 256
    __shared__ float red[16];
    float am0 = 0.f, am1 = 0.f, ac0 = 0.f, ac1 = 0.f;
    for (int h = 0; h < HH; h++) {
        size_t base = ((size_t)((bi >> 9) * HH + h) * LL + (bi & 511)) * LL;
        float v0 = g_scores[base + t];
        float v1 = g_scores[base + t + 256];
        float m = fmaxf(v0, v1);
        for (int o = 16; o; o >>= 1) m = fmaxf(m, __shfl_xor_sync(0xffffffffu, m, o));
        if ((t & 31) == 0) red[t >> 5] = m;
        __syncthreads();
        m = red[0];
        #pragma unroll
        for (int i = 1; i < 8; i++) m = fmaxf(m, red[i]);
        float e0 = __expf(v0 - m), e1 = __expf(v1 - m);
        float s = e0 + e1;
        for (int o = 16; o; o >>= 1) s += __shfl_xor_sync(0xffffffffu, s, o);
        if ((t & 31) == 0) red[8 + (t >> 5)] = s;
        __syncthreads();
        s = 0.f;
        #pragma unroll
        for (int i = 0; i < 8; i++) s += red[8 + i];
        float inv = 1.f / s;
        float ch = g_cbuf[h];
        am0 += 0.25f * e0 * inv; am1 += 0.25f * e1 * inv;
        ac0 += ch * e0 * inv;    ac1 += ch * e1 * inv;
        __syncthreads();
    }
    size_t ob = (size_t)bi * LL;
    g_adjm[ob + t] = am0; g_adjm[ob + t + 256] = am1;
    g_adjc[ob + t] = ac0; g_adjc[ob + t + 256] = ac1;
}

// ---------------- um/vm (per-token dots with b1m/b2m) ----------------
__global__ void umvm_kernel()
{
    int w = threadIdx.x >> 5, lane = threadIdx.x & 31;
    int row = blockIdx.x * 8 + w;
    const float* xr = g_x1 + (size_t)row * AA;
    float u = 0.f, v = 0.f;
    for (int c = lane; c < AA; c += 32) {
        float xv = xr[c];
        u += xv * g_b1m[c];
        v += xv * g_b2m[c];
    }
    for (int o = 16; o; o >>= 1) {
        u += __shfl_xor_sync(0xffffffffu, u, o);
        v += __shfl_xor_sync(0xffffffffu, v, o);
    }
    if (lane == 0) { g_um[row] = u; g_vm[row] = v; }
}

// ---------------- S[b,d] = sum_j x1 ; U[b,d] = sum_j um*x1 ----------------
__global__ void su_kernel()
{
    int b = blockIdx.x;
    int d = threadIdx.x;
    if (d >= AA) return;
    float s = 0.f, u = 0.f;
    for (int j = 0; j < LL; j++) {
        float xv = g_x1[(size_t)(b * LL + j) * AA + d];
        s += xv;
        u += g_um[b * LL + j] * xv;
    }
    g_S[b * AA + d] = s;
    g_U[b * AA + d] = u;
}

// ---------------- concat [x, x1, x2] -> feats ----------------
__global__ void concat_kernel()
{
    int idx = blockIdx.x * blockDim.x + threadIdx.x;
    if (idx >= BB * LL * AA) return;
    int row = idx / AA, d = idx % AA;
    g_feats[(size_t)row * (3 * AA) + d]          = g_x [idx];
    g_feats[(size_t)row * (3 * AA) + AA + d]     = g_x1[idx];
    g_feats[(size_t)row * (3 * AA) + 2 * AA + d] = g_x2[idx];
}

// ---------------- pooled = sum_l node / clip(sum mask,1) ----------------
__global__ void pool_kernel(const int* __restrict__ mask_ids)
{
    int b = blockIdx.x;
    __shared__ int redc[128];
    int t = threadIdx.x;   // 128
    int cnt = 0;
    for (int j = t; j < LL; j += 128) cnt += mask_ids[b * LL + j];
    redc[t] = cnt;
    __syncthreads();
    for (int o = 64; o; o >>= 1) { if (t < o) redc[t] += redc[t + o]; __syncthreads(); }
    float vl = fmaxf((float)redc[0], 1.f);
    if (t < AA) {
        float s = 0.f;
        for (int j = 0; j < LL; j++) s += g_node[(size_t)(b * LL + j) * AA + t];
        g_pooled[b * AA + t] = s / vl;
    }
}

// ---------------- logits ----------------
__global__ void logits_kernel(const float* __restrict__ cw, const float* __restrict__ cb,
                              float* __restrict__ out)
{
    int t = threadIdx.x;
    if (t >= BB * PP) return;
    int b = t / PP, p = t % PP;
    float s = cb[p];
    for (int d = 0; d < AA; d++) s += g_pooled[b * AA + d] * cw[p * AA + d];
    out[t] = s;
}

// ================================================================
extern "C" void kernel_launch(void* const* d_in, const int* in_sizes, int n_in,
                              void* d_out, int out_size)
{
    const float* seq     = (const float*)d_in[0];
    const float* syn     = (const float*)d_in[1];
    const float* ln_a    = (const float*)d_in[2];
    const float* ln_b    = (const float*)d_in[3];
    const float* Wxx_w   = (const float*)d_in[4];
    const float* Wxx_b   = (const float*)d_in[5];
    const float* q_w     = (const float*)d_in[6];
    const float* q_b     = (const float*)d_in[7];
    const float* k_w     = (const float*)d_in[8];
    const float* k_b     = (const float*)d_in[9];
    const float* W_w     = (const float*)d_in[10];
    const float* W_b     = (const float*)d_in[11];
    const float* Wx_w    = (const float*)d_in[12];
    const float* Wx_b    = (const float*)d_in[13];
    const float* agg_w   = (const float*)d_in[14];
    const float* agg_b   = (const float*)d_in[15];
    const float* cls_w   = (const float*)d_in[16];
    const float* cls_b   = (const float*)d_in[17];
    const int*   mask_ids= (const int*)d_in[18];
    const int*   src_mask= (const int*)d_in[19];
    float* out = (float*)d_out;

    float *p_seqn, *p_x, *p_q, *p_k, *p_Ax, *p_x1, *p_x2, *p_feats, *p_node;
    float *p_adjm, *p_adjc, *p_U, *p_S, *p_vm, *p_bm;
    cudaGetSymbolAddress((void**)&p_seqn, g_seqn);
    cudaGetSymbolAddress((void**)&p_x,    g_x);
    cudaGetSymbolAddress((void**)&p_q,    g_q);
    cudaGetSymbolAddress((void**)&p_k,    g_k);
    cudaGetSymbolAddress((void**)&p_Ax,   g_Ax);
    cudaGetSymbolAddress((void**)&p_x1,   g_x1);
    cudaGetSymbolAddress((void**)&p_x2,   g_x2);
    cudaGetSymbolAddress((void**)&p_feats,g_feats);
    cudaGetSymbolAddress((void**)&p_node, g_node);
    cudaGetSymbolAddress((void**)&p_adjm, g_adjm);
    cudaGetSymbolAddress((void**)&p_adjc, g_adjc);
    cudaGetSymbolAddress((void**)&p_U,    g_U);
    cudaGetSymbolAddress((void**)&p_S,    g_S);
    cudaGetSymbolAddress((void**)&p_vm,   g_vm);
    cudaGetSymbolAddress((void**)&p_bm,   g_bm);

    const int MROWS = BB * LL;          // 8192
    dim3 gemm_grid(2, MROWS / 64);      // N=100 -> 2 col tiles

    pre_kernel<<<1, 128>>>(Wx_w, Wx_b);
    ln_kernel<<<MROWS, 256>>>(seq, ln_a, ln_b);

    // x = seqn @ Wxx^T + b
    gemm_nt_kernel<<<gemm_grid, 256>>>(p_seqn, Wxx_w, Wxx_b, p_x, MROWS, AA, DD, 0);
    // q, k
    gemm_nt_kernel<<<gemm_grid, 256>>>(p_x, q_w, q_b, p_q, MROWS, AA, AA, 0);
    gemm_nt_kernel<<<gemm_grid, 256>>>(p_x, k_w, k_b, p_k, MROWS, AA, AA, 0);

    // scores
    scores_kernel<<<dim3(LL / 32, LL / 32, BB * HH), 256>>>(syn, src_mask);
    // softmax + head folding
    softmax_combine_kernel<<<MROWS, 256>>>();

    // layer 0: Ax1 = adjm @ x ; x1 = relu(Ax1 @ W^T + b)
    gemm_nn_b_kernel<<<dim3(2, LL / 64, BB), 256>>>(p_adjm, p_x, p_Ax,
        LL, AA, LL, LL * LL, LL * AA, LL * AA, nullptr, nullptr, nullptr, nullptr);
    gemm_nt_kernel<<<gemm_grid, 256>>>(p_Ax, W_w, W_b, p_x1, MROWS, AA, AA, 1);

    // rank-1 pieces of the implicit updated adjacency
    umvm_kernel<<<MROWS / 8, 256>>>();
    su_kernel<<<BB, 128>>>();

    // layer 1: Ax2 = adjc @ x1 + U + (vm+bm)*S ; x2 = relu(Ax2 @ W^T + b)
    gemm_nn_b_kernel<<<dim3(2, LL / 64, BB), 256>>>(p_adjc, p_x1, p_Ax,
        LL, AA, LL, LL * LL, LL * AA, LL * AA, p_U, p_S, p_vm, p_bm);
    gemm_nt_kernel<<<gemm_grid, 256>>>(p_Ax, W_w, W_b, p_x2, MROWS, AA, AA, 1);

    // aggregate
    concat_kernel<<<(BB * LL * AA + 255) / 256, 256>>>();
    gemm_nt_kernel<<<gemm_grid, 256>>>(p_feats, agg_w, agg_b, p_node, MROWS, AA, 3 * AA, 1);

    pool_kernel<<<BB, 128>>>(mask_ids);
    logits_kernel<<<1, 64>>>(cls_w, cls_b, out);
}